// round 1
// baseline (speedup 1.0000x reference)
#include <cuda_runtime.h>

// QHadamard: y = FWHT_4096(x) / 64, rows = batch*seq = 8192, DIM = 4096.
// Decomposition: H_4096 = H_64 (low 6 bits) then H_64 (high 6 bits).
// One block per row, 64 threads, 64 elements per thread, one smem transpose.

#define DIM 4096
#define THREADS 64

__device__ __forceinline__ void fwht64(float* x) {
#pragma unroll
    for (int h = 1; h < 64; h <<= 1) {
#pragma unroll
        for (int i = 0; i < 64; i += (h << 1)) {
#pragma unroll
            for (int j = i; j < i + h; ++j) {
                float a = x[j];
                float b = x[j + h];
                x[j]     = a + b;
                x[j + h] = a - b;
            }
        }
    }
}

__global__ void __launch_bounds__(THREADS)
QHadamard_24524263260380_kernel(const float* __restrict__ in,
                                float* __restrict__ out) {
    // One row (4096 floats) staged as 64 rows x 16 float4 in smem, with a
    // rotation swizzle for conflict-free transpose.
    __shared__ float4 s4[64 * 16];

    const int    t   = threadIdx.x;            // 0..63
    const size_t row = blockIdx.x;

    // ---- Pass 1: contiguous 64 elements per thread, FWHT-64 in registers ----
    const float4* g = reinterpret_cast<const float4*>(in) + row * (DIM / 4);

    float4 xv[16];
#pragma unroll
    for (int i = 0; i < 16; ++i) {
        xv[i] = g[t * 16 + i];                 // thread t covers elements [64t, 64t+64)
    }

    float* x = reinterpret_cast<float*>(xv);
    fwht64(x);

    // ---- Transpose via smem: write float4 with rotation slot=(i+t)&15 ----
    // Write phase: addr4 = 16*t + ((i+t)&15). Within each 8-thread phase the
    // addr4 mod 8 values are 8 consecutive integers mod 16 -> distinct mod 8:
    // conflict-free 128-bit stores.
#pragma unroll
    for (int i = 0; i < 16; ++i) {
        s4[t * 16 + ((i + t) & 15)] = xv[i];
    }
    __syncthreads();

    // ---- Pass 2: thread t gathers column b=t across all a (stride-64) ----
    // Element (a, b): float4 slot j0=b>>2 stored at ((j0+a)&15), component b&3.
    // Read bank = 4*((q+a)&7) + r for t=4q+r -> all 32 banks distinct: conflict-free.
    const float* sf = reinterpret_cast<const float*>(s4);
    float y[64];
#pragma unroll
    for (int a = 0; a < 64; ++a) {
        const int j = ((t >> 2) + a) & 15;
        y[a] = sf[a * 64 + j * 4 + (t & 3)];
    }

    fwht64(y);

    // ---- Store: out[row*4096 + 64a + t], scaled by 1/sqrt(4096) = 1/64 ----
    // Per step a, each warp writes 32 contiguous floats: fully coalesced.
    float* o = out + row * (size_t)DIM;
    const float scale = 0.015625f;             // 1/64
#pragma unroll
    for (int a = 0; a < 64; ++a) {
        o[a * 64 + t] = y[a] * scale;
    }
}

extern "C" void kernel_launch(void* const* d_in, const int* in_sizes, int n_in,
                              void* d_out, int out_size) {
    const float* x   = (const float*)d_in[0];
    float*       out = (float*)d_out;
    const int rows = in_sizes[0] / DIM;        // 4 * 2048 = 8192
    QHadamard_24524263260380_kernel<<<rows, THREADS>>>(x, out);
}

// round 2
// speedup vs baseline: 1.2908x; 1.2908x over previous
#include <cuda_runtime.h>

// QHadamard: y = FWHT_4096(x) / 64, rows = 8192, DIM = 4096.
// H_4096 = H_64 (low 6 bits) then H_64 (high 6 bits).
// One block per row, 64 threads, 64 elements/thread.
// All GMEM accesses coalesced; thread-private layout reached via smem staging.

#define DIM 4096
#define THREADS 64

__device__ __forceinline__ void fwht64(float* x) {
#pragma unroll
    for (int h = 1; h < 64; h <<= 1) {
#pragma unroll
        for (int i = 0; i < 64; i += (h << 1)) {
#pragma unroll
            for (int j = i; j < i + h; ++j) {
                float a = x[j];
                float b = x[j + h];
                x[j]     = a + b;
                x[j + h] = a - b;
            }
        }
    }
}

__global__ void __launch_bounds__(THREADS)
QHadamard_24524263260380_kernel(const float* __restrict__ in,
                                float* __restrict__ out) {
    // 64 rows x 16 float4 with rotation swizzle col' = (col + row) & 15.
    // Conflict-free for: coalesced staging writes, contiguous per-thread reads,
    // rotated transpose writes, and strided scalar reads (all verified mod-8 /
    // mod-32 bank analysis).
    __shared__ float4 s4[64 * 16];

    const int    t   = threadIdx.x;            // 0..63
    const size_t row = blockIdx.x;

    // ---- Stage 0: coalesced load -> swizzled smem ----
    // float4 index f = i*64 + t; smem slot = 16*(f>>4) + ((f&15) + (f>>4))&15.
    const float4* g = reinterpret_cast<const float4*>(in) + row * (DIM / 4);
#pragma unroll
    for (int i = 0; i < 16; ++i) {
        const int f = i * 64 + t;
        const int r = f >> 4;
        const int c = (f + r) & 15;            // (f&15 + r) & 15
        s4[r * 16 + c] = g[f];
    }
    __syncthreads();

    // ---- Pass 1: contiguous 64 elements per thread (f4 idx 16t..16t+15) ----
    float4 xv[16];
#pragma unroll
    for (int j = 0; j < 16; ++j) {
        xv[j] = s4[t * 16 + ((j + t) & 15)];
    }
    float* x = reinterpret_cast<float*>(xv);
    fwht64(x);
    __syncthreads();                           // WAR: all reads done before rewrite

    // ---- Transpose: rotated float4 writes (same swizzle family) ----
#pragma unroll
    for (int j = 0; j < 16; ++j) {
        s4[t * 16 + ((j + t) & 15)] = xv[j];
    }
    __syncthreads();

    // ---- Pass 2: thread t gathers column b=t across a (stride 64) ----
    // Element (a,b): float4 slot j0=b>>2 stored at ((j0+a)&15), comp b&3.
    const float* sf = reinterpret_cast<const float*>(s4);
    float y[64];
#pragma unroll
    for (int a = 0; a < 64; ++a) {
        const int j = ((t >> 2) + a) & 15;
        y[a] = sf[a * 64 + j * 4 + (t & 3)];
    }

    fwht64(y);

    // ---- Coalesced scaled store: out[row*4096 + 64a + t] ----
    float* o = out + row * (size_t)DIM;
    const float scale = 0.015625f;             // 1/64
#pragma unroll
    for (int a = 0; a < 64; ++a) {
        o[a * 64 + t] = y[a] * scale;
    }
}

extern "C" void kernel_launch(void* const* d_in, const int* in_sizes, int n_in,
                              void* d_out, int out_size) {
    const float* x   = (const float*)d_in[0];
    float*       out = (float*)d_out;
    const int rows = in_sizes[0] / DIM;        // 8192
    QHadamard_24524263260380_kernel<<<rows, THREADS>>>(x, out);
}

// round 3
// speedup vs baseline: 2.9796x; 2.3083x over previous
#include <cuda_runtime.h>

// QHadamard: y = FWHT_4096(x) / 64, rows = 8192, DIM = 4096.
// H_4096 = H_16(d2, stride 256) * H_16(d1, stride 16) * H_16(d0, stride 1);
// factors commute, applied d2 -> d1 -> d0.
// 256 threads/block, 16 elements/thread, one smem transpose, last digit via shfl.

#define DIM 4096
#define THREADS 256

__device__ __forceinline__ void fwht16(float* x) {
#pragma unroll
    for (int h = 1; h < 16; h <<= 1) {
#pragma unroll
        for (int i = 0; i < 16; i += (h << 1)) {
#pragma unroll
            for (int j = i; j < i + h; ++j) {
                float a = x[j];
                float b = x[j + h];
                x[j]     = a + b;
                x[j + h] = a - b;
            }
        }
    }
}

__global__ void __launch_bounds__(THREADS, 6)
QHadamard_24524263260380_kernel(const float* __restrict__ in,
                                float* __restrict__ out) {
    __shared__ float s[DIM];                   // 16 KB, plain e-index + XOR swizzle

    const int    T   = threadIdx.x;            // 0..255
    const size_t row = blockIdx.x;

    const float* g = in + row * (size_t)DIM;

    // ---- Pass 1: thread T owns e = k*256 + T (vary d2). Coalesced 128B/instr.
    float x[16];
#pragma unroll
    for (int k = 0; k < 16; ++k) {
        x[k] = g[k * 256 + T];
    }
    fwht16(x);                                 // FWHT over d2

    // ---- Transpose A->B via smem with XOR swizzle on d1's low bit ----
    // Logical element e = d2*256 + d1*16 + d0 stored at
    //   s[d2*256 + (d1 ^ (d2 & 1))*16 + d0].
    // Write (T = d1*16+d0, k = d2): banks ((d1^k)&1)*16 + d0 -> 32 distinct.
    const int w_hi = T >> 4;                   // d1
    const int w_lo = T & 15;                   // d0
#pragma unroll
    for (int k = 0; k < 16; ++k) {
        s[k * 256 + ((w_hi ^ (k & 1)) << 4) + w_lo] = x[k];
    }
    __syncthreads();

    // ---- Read B-ownership: thread T = d2*16 + d0, register r = d1 ----
    // Banks ((r^e2)&1)*16 + e0 across the warp's two e2 values -> 32 distinct.
    const int e2 = T >> 4;                     // d2
    const int e0 = T & 15;                     // d0
    float y[16];
#pragma unroll
    for (int r = 0; r < 16; ++r) {
        y[r] = s[e2 * 256 + ((r ^ (e2 & 1)) << 4) + e0];
    }

    fwht16(y);                                 // FWHT over d1

    // ---- Pass 3: FWHT over d0 = lane bits 0..3 via shfl_xor butterflies ----
    // bit clear: y = y + p ; bit set: y = p - y  ==>  y = fma(y, +/-1, p)
    const int lane = T & 31;
#pragma unroll
    for (int h = 1; h < 16; h <<= 1) {
        const float sgn = (lane & h) ? -1.0f : 1.0f;
#pragma unroll
        for (int r = 0; r < 16; ++r) {
            float p = __shfl_xor_sync(0xffffffffu, y[r], h);
            y[r] = fmaf(y[r], sgn, p);
        }
    }

    // ---- Scaled store: e = e2*256 + r*16 + e0 (two 64B segments / warp-instr)
    float* o = out + row * (size_t)DIM;
    const float scale = 0.015625f;             // 1/sqrt(4096)
#pragma unroll
    for (int r = 0; r < 16; ++r) {
        o[e2 * 256 + r * 16 + e0] = y[r] * scale;
    }
}

extern "C" void kernel_launch(void* const* d_in, const int* in_sizes, int n_in,
                              void* d_out, int out_size) {
    const float* x   = (const float*)d_in[0];
    float*       out = (float*)d_out;
    const int rows = in_sizes[0] / DIM;        // 8192
    QHadamard_24524263260380_kernel<<<rows, THREADS>>>(x, out);
}

// round 4
// speedup vs baseline: 3.5088x; 1.1776x over previous
#include <cuda_runtime.h>

// QHadamard: y = FWHT_4096(x) / 64, rows = 8192, DIM = 4096.
// 12 FWHT bit-stages split across 3 register passes, 2 smem transposes, 0 shuffles.
//   A: bits {5..9}  (owns e{0..4} via lanes, e{10,11} via warp id)
//   B: bits {0..4}  (owns 32 contiguous elements, f4 smem ops, in-place)
//   C: bits {10,11} (owns {0,1,9,10,11}; dense float4 stores)
// Smem swizzle: swz(e) = e ^ ((e & 0xE0) >> 3) -- conflict-free in all phases.

#define DIM 4096

__device__ __forceinline__ void bfly(float& a, float& b) {
    float t = a; a = t + b; b = t - b;
}

__device__ __forceinline__ void fwht32(float* x) {
#pragma unroll
    for (int h = 1; h < 32; h <<= 1)
#pragma unroll
        for (int i = 0; i < 32; i += (h << 1))
#pragma unroll
            for (int j = i; j < i + h; ++j) bfly(x[j], x[j + h]);
}

__global__ void __launch_bounds__(128, 8)
QHadamard_24524263260380_kernel(const float* __restrict__ in,
                                float* __restrict__ out) {
    __shared__ float s[DIM];                      // 16 KB, swizzled layout

    const int    T   = threadIdx.x;               // 0..127
    const size_t row = (size_t)blockIdx.x * DIM;
    const float* g   = in + row;

    // ---- Pass A: e = (T&31) + k*32 + (T>>5)*1024, k = 0..31 -> bits {5..9} ----
    const int abase = (T & 31) + ((T >> 5) << 10);
    float x[32];
#pragma unroll
    for (int k = 0; k < 32; ++k) x[k] = g[abase + (k << 5)];

    const float scale = 0.015625f;                // 1/sqrt(4096)
#pragma unroll
    for (int k = 0; k < 32; ++k) x[k] *= scale;

    fwht32(x);                                    // FWHT over bits 5..9

    // ---- T1 write: s[swz(e)], swz = e ^ ((k&7)<<2). Banks = lane ^ const. ----
#pragma unroll
    for (int k = 0; k < 32; ++k) {
        s[(abase + (k << 5)) ^ ((k & 7) << 2)] = x[k];
    }
    __syncthreads();

    // ---- Pass B: thread T = e>>5 owns 32 contiguous elements. f4 in/out. ----
    float y[32];
    {
        const int base4 = T * 8;                  // float4 index of e = T*32
        float4* s4 = reinterpret_cast<float4*>(s);
#pragma unroll
        for (int r = 0; r < 8; ++r) {
            float4 v = s4[base4 + (r ^ (T & 7))];
            y[r*4+0] = v.x; y[r*4+1] = v.y; y[r*4+2] = v.z; y[r*4+3] = v.w;
        }
        fwht32(y);                                // FWHT over bits 0..4
#pragma unroll
        for (int r = 0; r < 8; ++r) {
            s4[base4 + (r ^ (T & 7))] =
                make_float4(y[r*4+0], y[r*4+1], y[r*4+2], y[r*4+3]);
        }
    }
    __syncthreads();

    // ---- Pass C: base bits{2..6}=T&31, {7,8}=(T>>5)&3; owns {0,1,9,10,11} ----
    const int cbase4 = (T & 31) + (((T >> 5) & 3) << 5);   // float4 index
    const int cxor4  = (T >> 3) & 7;                       // swizzle in f4 units
    float z[32];
    {
        const float4* s4 = reinterpret_cast<const float4*>(s);
#pragma unroll
        for (int rr = 0; rr < 4; ++rr)
#pragma unroll
            for (int s9 = 0; s9 < 2; ++s9) {
                float4 v = s4[(cbase4 + (s9 << 7) + (rr << 8)) ^ cxor4];
                const int i = (rr << 3) + (s9 << 2);
                z[i] = v.x; z[i+1] = v.y; z[i+2] = v.z; z[i+3] = v.w;
            }
    }
    // FWHT over bits {10,11} = z-index bits {3,4}
#pragma unroll
    for (int hi = 0; hi < 32; hi += 16)
#pragma unroll
        for (int j = 0; j < 8; ++j) bfly(z[hi + j], z[hi + j + 8]);
#pragma unroll
    for (int j = 0; j < 16; ++j) bfly(z[j], z[j + 16]);

    // ---- Dense float4 stores: per instr lanes write 32 contiguous float4 ----
    float4* o4 = reinterpret_cast<float4*>(out + row);
#pragma unroll
    for (int rr = 0; rr < 4; ++rr)
#pragma unroll
        for (int s9 = 0; s9 < 2; ++s9) {
            const int i = (rr << 3) + (s9 << 2);
            o4[cbase4 + (s9 << 7) + (rr << 8)] =
                make_float4(z[i], z[i+1], z[i+2], z[i+3]);
        }
}

extern "C" void kernel_launch(void* const* d_in, const int* in_sizes, int n_in,
                              void* d_out, int out_size) {
    const float* x   = (const float*)d_in[0];
    float*       out = (float*)d_out;
    const int rows = in_sizes[0] / DIM;            // 8192
    QHadamard_24524263260380_kernel<<<rows, 128>>>(x, out);
}